// round 2
// baseline (speedup 1.0000x reference)
#include <cuda_runtime.h>
#include <math.h>

#define BM 128
#define BN 128
#define BK 8
#define PAD 4

#define NB  16
#define SEQ 1024
#define HID 768
#define SCALE 0.03608439182435161f  /* 1/sqrt(768) */

// Scratch (device globals: allocation-free per harness rules)
__device__ float g_q [(size_t)NB*SEQ*HID];
__device__ float g_k [(size_t)NB*SEQ*HID];
__device__ float g_v [(size_t)NB*SEQ*HID];
__device__ float g_sc[(size_t)NB*SEQ*SEQ];
__device__ float g_o [(size_t)NB*SEQ*HID];
__device__ float g_h1[(size_t)NB*SEQ*HID];

// ---------------------------------------------------------------------------
// NT GEMM: C[M,N] = act(A[M,K] * W[N,K]^T + bias) (+ res). All dims % tile == 0.
// ---------------------------------------------------------------------------
__global__ __launch_bounds__(256) void gemm_nt_kernel(
    const float* __restrict__ A, const float* __restrict__ W,
    const float* __restrict__ bias, const float* __restrict__ res,
    float* __restrict__ C, int M, int N, int K, int relu)
{
    __shared__ float As[BK][BM + PAD];
    __shared__ float Bs[BK][BN + PAD];

    const int bm = blockIdx.y * BM;
    const int bn = blockIdx.x * BN;
    const int tid = threadIdx.x;

    const int ldrow = tid >> 1;          // 0..127
    const int ldk   = (tid & 1) << 2;    // 0 or 4
    const float* Ap = A + (size_t)(bm + ldrow) * K + ldk;
    const float* Wp = W + (size_t)(bn + ldrow) * K + ldk;

    const int ty = tid >> 4;             // 0..15 -> rows ty*8..ty*8+7
    const int tx = tid & 15;             // cols tx + j*16

    float acc[8][8];
    #pragma unroll
    for (int i = 0; i < 8; i++)
        #pragma unroll
        for (int j = 0; j < 8; j++) acc[i][j] = 0.f;

    for (int k0 = 0; k0 < K; k0 += BK) {
        float4 av = *reinterpret_cast<const float4*>(Ap + k0);
        float4 wv = *reinterpret_cast<const float4*>(Wp + k0);
        As[ldk+0][ldrow] = av.x; As[ldk+1][ldrow] = av.y;
        As[ldk+2][ldrow] = av.z; As[ldk+3][ldrow] = av.w;
        Bs[ldk+0][ldrow] = wv.x; Bs[ldk+1][ldrow] = wv.y;
        Bs[ldk+2][ldrow] = wv.z; Bs[ldk+3][ldrow] = wv.w;
        __syncthreads();

        #pragma unroll
        for (int kk = 0; kk < BK; kk++) {
            float a[8], b[8];
            float4 a0 = *reinterpret_cast<const float4*>(&As[kk][ty*8]);
            float4 a1 = *reinterpret_cast<const float4*>(&As[kk][ty*8+4]);
            a[0]=a0.x; a[1]=a0.y; a[2]=a0.z; a[3]=a0.w;
            a[4]=a1.x; a[5]=a1.y; a[6]=a1.z; a[7]=a1.w;
            #pragma unroll
            for (int j = 0; j < 8; j++) b[j] = Bs[kk][tx + j*16];
            #pragma unroll
            for (int i = 0; i < 8; i++)
                #pragma unroll
                for (int j = 0; j < 8; j++)
                    acc[i][j] = fmaf(a[i], b[j], acc[i][j]);
        }
        __syncthreads();
    }

    #pragma unroll
    for (int i = 0; i < 8; i++) {
        const int row = bm + ty*8 + i;
        float* Crow = C + (size_t)row * N;
        const float* Rrow = res ? (res + (size_t)row * N) : nullptr;
        #pragma unroll
        for (int j = 0; j < 8; j++) {
            const int col = bn + tx + j*16;
            float v = acc[i][j] + bias[col];
            if (relu) v = fmaxf(v, 0.f);
            if (Rrow) v += Rrow[col];
            Crow[col] = v;
        }
    }
}

// ---------------------------------------------------------------------------
// Batched score GEMM: S[b,s,t] = (q[b,s,:].k[b,t,:])*SCALE - (1-m_s*m_t)*1e12
// ---------------------------------------------------------------------------
__global__ __launch_bounds__(256) void score_gemm_kernel(
    const float* __restrict__ Q, const float* __restrict__ Kt,
    const int* __restrict__ mask, float* __restrict__ Sc)
{
    __shared__ float As[BK][BM + PAD];
    __shared__ float Bs[BK][BN + PAD];

    const int b  = blockIdx.z;
    const float* A = Q  + (size_t)b * SEQ * HID;
    const float* W = Kt + (size_t)b * SEQ * HID;
    float* C = Sc + (size_t)b * SEQ * SEQ;
    const int* mrow = mask + (size_t)b * SEQ;

    const int bm = blockIdx.y * BM;
    const int bn = blockIdx.x * BN;
    const int tid = threadIdx.x;
    const int ldrow = tid >> 1;
    const int ldk   = (tid & 1) << 2;
    const float* Ap = A + (size_t)(bm + ldrow) * HID + ldk;
    const float* Wp = W + (size_t)(bn + ldrow) * HID + ldk;
    const int ty = tid >> 4;
    const int tx = tid & 15;

    float acc[8][8];
    #pragma unroll
    for (int i = 0; i < 8; i++)
        #pragma unroll
        for (int j = 0; j < 8; j++) acc[i][j] = 0.f;

    for (int k0 = 0; k0 < HID; k0 += BK) {
        float4 av = *reinterpret_cast<const float4*>(Ap + k0);
        float4 wv = *reinterpret_cast<const float4*>(Wp + k0);
        As[ldk+0][ldrow] = av.x; As[ldk+1][ldrow] = av.y;
        As[ldk+2][ldrow] = av.z; As[ldk+3][ldrow] = av.w;
        Bs[ldk+0][ldrow] = wv.x; Bs[ldk+1][ldrow] = wv.y;
        Bs[ldk+2][ldrow] = wv.z; Bs[ldk+3][ldrow] = wv.w;
        __syncthreads();
        #pragma unroll
        for (int kk = 0; kk < BK; kk++) {
            float a[8], bb[8];
            float4 a0 = *reinterpret_cast<const float4*>(&As[kk][ty*8]);
            float4 a1 = *reinterpret_cast<const float4*>(&As[kk][ty*8+4]);
            a[0]=a0.x; a[1]=a0.y; a[2]=a0.z; a[3]=a0.w;
            a[4]=a1.x; a[5]=a1.y; a[6]=a1.z; a[7]=a1.w;
            #pragma unroll
            for (int j = 0; j < 8; j++) bb[j] = Bs[kk][tx + j*16];
            #pragma unroll
            for (int i = 0; i < 8; i++)
                #pragma unroll
                for (int j = 0; j < 8; j++)
                    acc[i][j] = fmaf(a[i], bb[j], acc[i][j]);
        }
        __syncthreads();
    }

    float mr[8], mc[8];
    #pragma unroll
    for (int i = 0; i < 8; i++) mr[i] = (float)mrow[bm + ty*8 + i];
    #pragma unroll
    for (int j = 0; j < 8; j++) mc[j] = (float)mrow[bn + tx + j*16];

    #pragma unroll
    for (int i = 0; i < 8; i++) {
        const int row = bm + ty*8 + i;
        float* Crow = C + (size_t)row * SEQ;
        #pragma unroll
        for (int j = 0; j < 8; j++) {
            const int col = bn + tx + j*16;
            float s = acc[i][j] * SCALE - (1.0f - mr[i]*mc[j]) * 1e12f;
            Crow[col] = s;
        }
    }
}

// ---------------------------------------------------------------------------
// Batched NN GEMM: O[b,s,h] = sum_t Wgt[b,s,t] * V[b,t,h]
// ---------------------------------------------------------------------------
__global__ __launch_bounds__(256) void gemm_nn_kernel(
    const float* __restrict__ Wgt, const float* __restrict__ V,
    float* __restrict__ O)
{
    __shared__ float As[BK][BM + PAD];
    __shared__ float Bs[BK][BN + PAD];

    const int b = blockIdx.z;
    const float* A  = Wgt + (size_t)b * SEQ * SEQ;   // [SEQ, SEQ] K-major
    const float* Bv = V   + (size_t)b * SEQ * HID;   // [SEQ(K), HID(N)] N-major
    float* C = O + (size_t)b * SEQ * HID;
    const int M = SEQ, N = HID, K = SEQ;

    const int bm = blockIdx.y * BM;
    const int bn = blockIdx.x * BN;
    const int tid = threadIdx.x;

    const int ldrow = tid >> 1;
    const int ldk   = (tid & 1) << 2;
    const float* Ap = A + (size_t)(bm + ldrow) * K + ldk;

    const int brow  = tid >> 5;          // 0..7  (k row within tile)
    const int bcol4 = (tid & 31) << 2;   // 0..124
    const float* Bp = Bv + (size_t)brow * N + bn + bcol4;

    const int ty = tid >> 4;
    const int tx = tid & 15;

    float acc[8][8];
    #pragma unroll
    for (int i = 0; i < 8; i++)
        #pragma unroll
        for (int j = 0; j < 8; j++) acc[i][j] = 0.f;

    for (int k0 = 0; k0 < K; k0 += BK) {
        float4 av = *reinterpret_cast<const float4*>(Ap + k0);
        float4 bv4 = *reinterpret_cast<const float4*>(Bp + (size_t)k0 * N);
        As[ldk+0][ldrow] = av.x; As[ldk+1][ldrow] = av.y;
        As[ldk+2][ldrow] = av.z; As[ldk+3][ldrow] = av.w;
        *reinterpret_cast<float4*>(&Bs[brow][bcol4]) = bv4;
        __syncthreads();
        #pragma unroll
        for (int kk = 0; kk < BK; kk++) {
            float a[8], bb[8];
            float4 a0 = *reinterpret_cast<const float4*>(&As[kk][ty*8]);
            float4 a1 = *reinterpret_cast<const float4*>(&As[kk][ty*8+4]);
            a[0]=a0.x; a[1]=a0.y; a[2]=a0.z; a[3]=a0.w;
            a[4]=a1.x; a[5]=a1.y; a[6]=a1.z; a[7]=a1.w;
            #pragma unroll
            for (int j = 0; j < 8; j++) bb[j] = Bs[kk][tx + j*16];
            #pragma unroll
            for (int i = 0; i < 8; i++)
                #pragma unroll
                for (int j = 0; j < 8; j++)
                    acc[i][j] = fmaf(a[i], bb[j], acc[i][j]);
        }
        __syncthreads();
    }

    #pragma unroll
    for (int i = 0; i < 8; i++) {
        const int row = bm + ty*8 + i;
        float* Crow = C + (size_t)row * N;
        #pragma unroll
        for (int j = 0; j < 8; j++)
            Crow[bn + tx + j*16] = acc[i][j];
    }
}

// ---------------------------------------------------------------------------
// Row softmax over t (len SEQ) with mask multiply. One block per (b,row).
// ---------------------------------------------------------------------------
__global__ __launch_bounds__(256) void softmax_kernel(
    float* __restrict__ Sc, const int* __restrict__ mask)
{
    const int b = blockIdx.y, row = blockIdx.x, tid = threadIdx.x;
    float* srow = Sc + ((size_t)b * SEQ + row) * SEQ;
    const int* mrow = mask + (size_t)b * SEQ;

    float4 x = *reinterpret_cast<const float4*>(srow + tid*4);

    float mx = fmaxf(fmaxf(x.x, x.y), fmaxf(x.z, x.w));
    #pragma unroll
    for (int o = 16; o > 0; o >>= 1)
        mx = fmaxf(mx, __shfl_xor_sync(0xffffffffu, mx, o));

    __shared__ float red[8];
    if ((tid & 31) == 0) red[tid >> 5] = mx;
    __syncthreads();
    float rmx = red[0];
    #pragma unroll
    for (int i = 1; i < 8; i++) rmx = fmaxf(rmx, red[i]);

    float e0 = expf(x.x - rmx), e1 = expf(x.y - rmx);
    float e2 = expf(x.z - rmx), e3 = expf(x.w - rmx);
    float s = e0 + e1 + e2 + e3;
    #pragma unroll
    for (int o = 16; o > 0; o >>= 1)
        s += __shfl_xor_sync(0xffffffffu, s, o);
    __syncthreads();
    if ((tid & 31) == 0) red[tid >> 5] = s;
    __syncthreads();
    float tot = red[0];
    #pragma unroll
    for (int i = 1; i < 8; i++) tot += red[i];

    const float c = (1.0f / tot) * (float)mrow[row];
    float4 o4;
    o4.x = e0 * c * (float)mrow[tid*4 + 0];
    o4.y = e1 * c * (float)mrow[tid*4 + 1];
    o4.z = e2 * c * (float)mrow[tid*4 + 2];
    o4.w = e3 * c * (float)mrow[tid*4 + 3];
    *reinterpret_cast<float4*>(srow + tid*4) = o4;
}

// ---------------------------------------------------------------------------
extern "C" void kernel_launch(void* const* d_in, const int* in_sizes, int n_in,
                              void* d_out, int out_size)
{
    const float* x    = (const float*)d_in[0];
    const int*   mask = (const int*)  d_in[1];
    const float* Wq = (const float*)d_in[2];
    const float* bq = (const float*)d_in[3];
    const float* Wk = (const float*)d_in[4];
    const float* bk = (const float*)d_in[5];
    const float* Wv = (const float*)d_in[6];
    const float* bv = (const float*)d_in[7];
    const float* W1 = (const float*)d_in[8];
    const float* b1 = (const float*)d_in[9];
    const float* W2 = (const float*)d_in[10];
    const float* b2 = (const float*)d_in[11];
    float* out = (float*)d_out;

    float *q, *k, *v, *sc, *o, *h1;
    cudaGetSymbolAddress((void**)&q,  g_q);
    cudaGetSymbolAddress((void**)&k,  g_k);
    cudaGetSymbolAddress((void**)&v,  g_v);
    cudaGetSymbolAddress((void**)&sc, g_sc);
    cudaGetSymbolAddress((void**)&o,  g_o);
    cudaGetSymbolAddress((void**)&h1, g_h1);

    dim3 blk(256);
    const int M = NB * SEQ;                 // 16384
    dim3 gproj(HID / BN, M / BM);           // (6, 128)

    gemm_nt_kernel<<<gproj, blk>>>(x, Wq, bq, nullptr, q, M, HID, HID, 1);
    gemm_nt_kernel<<<gproj, blk>>>(x, Wk, bk, nullptr, k, M, HID, HID, 1);
    gemm_nt_kernel<<<gproj, blk>>>(x, Wv, bv, nullptr, v, M, HID, HID, 0);

    dim3 gsc(SEQ / BN, SEQ / BM, NB);       // (8, 8, 16)
    score_gemm_kernel<<<gsc, blk>>>(q, k, mask, sc);

    softmax_kernel<<<dim3(SEQ, NB), blk>>>(sc, mask);

    dim3 gwv(HID / BN, SEQ / BM, NB);       // (6, 8, 16)
    gemm_nn_kernel<<<gwv, blk>>>(sc, v, o);

    gemm_nt_kernel<<<gproj, blk>>>(o,  W1, b1, nullptr, h1, M, HID, HID, 1);
    gemm_nt_kernel<<<gproj, blk>>>(h1, W2, b2, o,      out, M, HID, HID, 0);
}

// round 4
// speedup vs baseline: 2.3336x; 2.3336x over previous
#include <cuda_runtime.h>
#include <cuda_bf16.h>
#include <cstdint>

#define NB   16
#define SEQ  1024
#define HID  768
#define SCALE_QK 0.03608439182435161f

#define BM 128
#define BN 128
#define BK 32
#define NTHREADS 256
#define STG 10240            /* bytes per hi or lo tile buffer */
#define STAGE_BYTES 40960    /* Ah,Al,Bh,Bl */
#define NSTAGES 3
#define SMEM_GEMM (NSTAGES*STAGE_BYTES)

typedef __nv_bfloat16 bf16;

/* ------------------ scratch (device globals) ------------------ */
#define NXE 12582912   /* 16*1024*768 */
#define NWE 589824     /* 768*768 */
#define NSE 16777216   /* 16*1024*1024 */
__device__ bf16 g_xh[NXE],  g_xl[NXE];
__device__ bf16 g_qh[NXE],  g_ql[NXE];
__device__ bf16 g_kh[NXE],  g_kl[NXE];
__device__ bf16 g_vh[NXE],  g_vl[NXE];
__device__ bf16 g_oh[NXE],  g_ol[NXE];
__device__ bf16 g_h1h[NXE], g_h1l[NXE];
__device__ bf16 g_wqh[NWE], g_wql[NWE], g_wkh[NWE], g_wkl[NWE], g_wvh[NWE], g_wvl[NWE];
__device__ bf16 g_w1h[NWE], g_w1l[NWE], g_w2h[NWE], g_w2l[NWE];
__device__ float g_sc[NSE];
__device__ bf16 g_wh[NSE],  g_wl[NSE];
__device__ float g_of[NXE];

/* ------------------ helpers ------------------ */
static __device__ __forceinline__ uint32_t smem_u32(const void* p) {
    uint32_t a;
    asm("{ .reg .u64 t; cvta.to.shared.u64 t, %1; cvt.u32.u64 %0, t; }" : "=r"(a) : "l"(p));
    return a;
}
static __device__ __forceinline__ uint32_t pack_bf2(float v0, float v1) {
    uint32_t d;  /* d.hi = cvt(v1), d.lo = cvt(v0)  -> memory order v0,v1 */
    asm("cvt.rn.bf16x2.f32 %0, %1, %2;" : "=r"(d) : "f"(v1), "f"(v0));
    return d;
}
static __device__ __forceinline__ void split2(float v0, float v1, uint32_t& h, uint32_t& l) {
    h = pack_bf2(v0, v1);
    float h0 = __uint_as_float(h << 16);
    float h1 = __uint_as_float(h & 0xFFFF0000u);
    l = pack_bf2(v0 - h0, v1 - h1);
}

#define CP16(dst, src) \
    asm volatile("cp.async.cg.shared.global [%0], [%1], 16;" :: "r"(dst), "l"(src))
#define CPCOMMIT() asm volatile("cp.async.commit_group;" ::: "memory")
#define CPWAIT2()  asm volatile("cp.async.wait_group 2;" ::: "memory")

#define LDSM4(r, a) \
    asm volatile("ldmatrix.sync.aligned.m8n8.x4.shared.b16 {%0,%1,%2,%3}, [%4];" \
        : "=r"((r)[0]),"=r"((r)[1]),"=r"((r)[2]),"=r"((r)[3]) : "r"(a))
#define LDSM4T(r, a) \
    asm volatile("ldmatrix.sync.aligned.m8n8.x4.trans.shared.b16 {%0,%1,%2,%3}, [%4];" \
        : "=r"((r)[0]),"=r"((r)[1]),"=r"((r)[2]),"=r"((r)[3]) : "r"(a))
#define MMA(c, a, b0, b1) \
    asm volatile("mma.sync.aligned.m16n8k16.row.col.f32.bf16.bf16.f32 " \
        "{%0,%1,%2,%3}, {%4,%5,%6,%7}, {%8,%9}, {%0,%1,%2,%3};" \
        : "+f"((c)[0]), "+f"((c)[1]), "+f"((c)[2]), "+f"((c)[3]) \
        : "r"((a)[0]),"r"((a)[1]),"r"((a)[2]),"r"((a)[3]), "r"(b0), "r"(b1))

/* fp32 -> bf16 hi/lo conversion (pre-pass) */
__global__ __launch_bounds__(256) void cvt_kernel(
    const float* __restrict__ in, uint32_t* __restrict__ oh,
    uint32_t* __restrict__ ol, int n2)
{
    int i = blockIdx.x * 256 + threadIdx.x;
    if (i < n2) {
        float2 v = reinterpret_cast<const float2*>(in)[i];
        uint32_t h, l; split2(v.x, v.y, h, l);
        oh[i] = h; ol[i] = l;
    }
}

/* ---------------------------------------------------------------------------
 * bf16 split GEMM, mma.sync m16n8k16, 128x128x32 tiles, 3-stage cp.async.
 * nn=0: C = A[M,K] * B[N,K]^T ; nn=1: C = A[M,K] * B[K,N] (ldbn = row stride).
 * Epilogue: mask!=0 -> score mode (scale+penalty, fp32 out only).
 * Else: +bias, relu, +res(fp32); writes Cf (fp32) and/or Ch/Cl (bf16 hi/lo).
 * ------------------------------------------------------------------------ */
__global__ __launch_bounds__(NTHREADS) void gemm_bf(
    const bf16* __restrict__ Ah, const bf16* __restrict__ Al,
    const bf16* __restrict__ Bh, const bf16* __restrict__ Bl,
    int K, int nn, int ldbn,
    size_t sA, size_t sB, size_t sC,
    float* __restrict__ Cf, bf16* __restrict__ Ch, bf16* __restrict__ Cl,
    int ldc, const float* __restrict__ bias, const float* __restrict__ res,
    const int* __restrict__ mask, int relu)
{
    extern __shared__ char smraw[];
    const uint32_t sb = smem_u32(smraw);
    const int tid = threadIdx.x, lane = tid & 31, wid = tid >> 5;
    const int wm = wid >> 1, wn = wid & 1;
    const int z = blockIdx.z, bm = blockIdx.y * BM, bn = blockIdx.x * BN;

    const bf16* Ahg = Ah + z * sA + (size_t)bm * K;
    const bf16* Alg = Al + z * sA + (size_t)bm * K;
    const bf16 *Bhg, *Blg;
    if (nn) { Bhg = Bh + z * sB + bn;              Blg = Bl + z * sB + bn; }
    else    { Bhg = Bh + z * sB + (size_t)bn * K;  Blg = Bl + z * sB + (size_t)bn * K; }

    float acc[2][8][4];
    #pragma unroll
    for (int i = 0; i < 2; i++)
        #pragma unroll
        for (int j = 0; j < 8; j++)
            #pragma unroll
            for (int t = 0; t < 4; t++) acc[i][j][t] = 0.f;

    auto issue = [&](int s) {
        const uint32_t stb = sb + (uint32_t)(s % NSTAGES) * STAGE_BYTES;
        const int k0 = s * BK;
        #pragma unroll
        for (int i = 0; i < 2; i++) {
            const int idx = tid + (i << 8);
            const int row = idx >> 2, c8 = (idx & 3) << 3;
            const uint32_t da = stb + row * 80 + (c8 << 1);
            CP16(da,       Ahg + (size_t)row * K + k0 + c8);
            CP16(da + STG, Alg + (size_t)row * K + k0 + c8);
        }
        if (!nn) {
            #pragma unroll
            for (int i = 0; i < 2; i++) {
                const int idx = tid + (i << 8);
                const int row = idx >> 2, c8 = (idx & 3) << 3;
                const uint32_t db = stb + 2 * STG + row * 80 + (c8 << 1);
                CP16(db,       Bhg + (size_t)row * K + k0 + c8);
                CP16(db + STG, Blg + (size_t)row * K + k0 + c8);
            }
        } else {
            #pragma unroll
            for (int i = 0; i < 2; i++) {
                const int idx = tid + (i << 8);
                const int row = idx >> 4, c8 = (idx & 15) << 3;
                const uint32_t db = stb + 2 * STG + row * 272 + (c8 << 1);
                CP16(db,       Bhg + (size_t)(k0 + row) * ldbn + c8);
                CP16(db + STG, Blg + (size_t)(k0 + row) * ldbn + c8);
            }
        }
    };

    auto compute = [&](int s) {
        const uint32_t stb = sb + (uint32_t)(s % NSTAGES) * STAGE_BYTES;
        #pragma unroll
        for (int ks = 0; ks < 2; ks++) {
            uint32_t ah[2][4], al[2][4], bh[4][4], bl[4][4];
            #pragma unroll
            for (int i = 0; i < 2; i++) {
                const int arow = wm * 32 + i * 16 + (lane & 15);
                const uint32_t ad = stb + arow * 80 + ((ks * 16 + ((lane >> 4) << 3)) << 1);
                LDSM4(ah[i], ad);
                LDSM4(al[i], ad + STG);
            }
            if (!nn) {
                #pragma unroll
                for (int p = 0; p < 4; p++) {
                    const int brow = wn * 64 + p * 16 + (lane & 7) + ((lane >> 4) << 3);
                    const uint32_t bd = stb + 2 * STG + brow * 80 +
                                        ((ks * 16 + (((lane >> 3) & 1) << 3)) << 1);
                    LDSM4(bh[p], bd);
                    LDSM4(bl[p], bd + STG);
                }
            } else {
                #pragma unroll
                for (int p = 0; p < 4; p++) {
                    const int krow = ks * 16 + (lane & 7) + (((lane >> 3) & 1) << 3);
                    const int ncol = wn * 64 + p * 16 + ((lane >> 4) << 3);
                    const uint32_t bd = stb + 2 * STG + krow * 272 + (ncol << 1);
                    LDSM4T(bh[p], bd);
                    LDSM4T(bl[p], bd + STG);
                }
            }
            #pragma unroll
            for (int i = 0; i < 2; i++)
                #pragma unroll
                for (int j = 0; j < 8; j++) {
                    const uint32_t b0h = bh[j >> 1][(j & 1) * 2], b1h = bh[j >> 1][(j & 1) * 2 + 1];
                    const uint32_t b0l = bl[j >> 1][(j & 1) * 2], b1l = bl[j >> 1][(j & 1) * 2 + 1];
                    MMA(acc[i][j], ah[i], b0h, b1h);
                    MMA(acc[i][j], ah[i], b0l, b1l);
                    MMA(acc[i][j], al[i], b0h, b1h);
                }
        }
    };

    const int NSt = K / BK;
    issue(0); CPCOMMIT();
    issue(1); CPCOMMIT();
    for (int s = 0; s < NSt; s++) {
        if (s + 2 < NSt) issue(s + 2);
        CPCOMMIT();
        CPWAIT2();
        __syncthreads();
        compute(s);
        __syncthreads();
    }

    /* ---- epilogue ---- */
    const int* mk = mask ? (mask + (size_t)z * SEQ) : (const int*)0;
    float* Cfz = Cf ? (Cf + z * sC) : (float*)0;
    bf16*  Chz = Ch ? (Ch + z * sC) : (bf16*)0;
    bf16*  Clz = Cl ? (Cl + z * sC) : (bf16*)0;
    const float* rz = res ? (res + z * sC) : (const float*)0;

    #pragma unroll
    for (int i = 0; i < 2; i++) {
        const int r0 = bm + wm * 32 + i * 16 + (lane >> 2);
        #pragma unroll
        for (int j = 0; j < 8; j++) {
            const int c = bn + wn * 64 + j * 8 + ((lane & 3) << 1);
            float ax = acc[i][j][0], ay = acc[i][j][1];
            float az = acc[i][j][2], aw = acc[i][j][3];
            if (mk) {
                const float mc0 = (float)mk[c], mc1 = (float)mk[c + 1];
                const float m0 = (float)mk[r0], m1 = (float)mk[r0 + 8];
                ax = ax * SCALE_QK - (1.f - m0 * mc0) * 1e12f;
                ay = ay * SCALE_QK - (1.f - m0 * mc1) * 1e12f;
                az = az * SCALE_QK - (1.f - m1 * mc0) * 1e12f;
                aw = aw * SCALE_QK - (1.f - m1 * mc1) * 1e12f;
            } else {
                if (bias) {
                    const float b0 = bias[c], b1 = bias[c + 1];
                    ax += b0; ay += b1; az += b0; aw += b1;
                }
                if (relu) {
                    ax = fmaxf(ax, 0.f); ay = fmaxf(ay, 0.f);
                    az = fmaxf(az, 0.f); aw = fmaxf(aw, 0.f);
                }
                if (rz) {
                    const float2 q0 = *(const float2*)&rz[(size_t)r0 * ldc + c];
                    const float2 q1 = *(const float2*)&rz[(size_t)(r0 + 8) * ldc + c];
                    ax += q0.x; ay += q0.y; az += q1.x; aw += q1.y;
                }
            }
            const size_t o0 = (size_t)r0 * ldc + c, o1 = o0 + (size_t)8 * ldc;
            if (Cfz) {
                *(float2*)&Cfz[o0] = make_float2(ax, ay);
                *(float2*)&Cfz[o1] = make_float2(az, aw);
            }
            if (Chz) {
                uint32_t h, l;
                split2(ax, ay, h, l);
                *(uint32_t*)((char*)Chz + o0 * 2) = h;
                *(uint32_t*)((char*)Clz + o0 * 2) = l;
                split2(az, aw, h, l);
                *(uint32_t*)((char*)Chz + o1 * 2) = h;
                *(uint32_t*)((char*)Clz + o1 * 2) = l;
            }
        }
    }
}

/* ---- row softmax, fp32 in -> bf16 hi/lo out, fused mask ---- */
__global__ __launch_bounds__(256) void softmax_kernel(
    const float* __restrict__ Sc, bf16* __restrict__ Wh, bf16* __restrict__ Wl,
    const int* __restrict__ mask)
{
    const int b = blockIdx.y, row = blockIdx.x, tid = threadIdx.x;
    const float* srow = Sc + ((size_t)b * SEQ + row) * SEQ;
    const int* mrow = mask + (size_t)b * SEQ;
    float4 x = *(const float4*)(srow + tid * 4);

    float mx = fmaxf(fmaxf(x.x, x.y), fmaxf(x.z, x.w));
    #pragma unroll
    for (int o = 16; o > 0; o >>= 1) mx = fmaxf(mx, __shfl_xor_sync(~0u, mx, o));
    __shared__ float red[8];
    if ((tid & 31) == 0) red[tid >> 5] = mx;
    __syncthreads();
    float rmx = red[0];
    #pragma unroll
    for (int i = 1; i < 8; i++) rmx = fmaxf(rmx, red[i]);

    float e0 = expf(x.x - rmx), e1 = expf(x.y - rmx);
    float e2 = expf(x.z - rmx), e3 = expf(x.w - rmx);
    float s = e0 + e1 + e2 + e3;
    #pragma unroll
    for (int o = 16; o > 0; o >>= 1) s += __shfl_xor_sync(~0u, s, o);
    __syncthreads();
    if ((tid & 31) == 0) red[tid >> 5] = s;
    __syncthreads();
    float tot = red[0];
    #pragma unroll
    for (int i = 1; i < 8; i++) tot += red[i];

    const float cns = (1.0f / tot) * (float)mrow[row];
    const float o0 = e0 * cns * (float)mrow[tid * 4 + 0];
    const float o1 = e1 * cns * (float)mrow[tid * 4 + 1];
    const float o2 = e2 * cns * (float)mrow[tid * 4 + 2];
    const float o3 = e3 * cns * (float)mrow[tid * 4 + 3];

    uint32_t h0, l0, h1, l1;
    split2(o0, o1, h0, l0);
    split2(o2, o3, h1, l1);
    const size_t off = (((size_t)b * SEQ + row) * SEQ + tid * 4) * 2;
    *(uint2*)((char*)Wh + off) = make_uint2(h0, h1);
    *(uint2*)((char*)Wl + off) = make_uint2(l0, l1);
}

/* --------------------------------------------------------------------- */
extern "C" void kernel_launch(void* const* d_in, const int* in_sizes, int n_in,
                              void* d_out, int out_size)
{
    const float* x    = (const float*)d_in[0];
    const int*   mask = (const int*)  d_in[1];
    const float* Wq = (const float*)d_in[2];
    const float* bq = (const float*)d_in[3];
    const float* Wk = (const float*)d_in[4];
    const float* bk = (const float*)d_in[5];
    const float* Wv = (const float*)d_in[6];
    const float* bv = (const float*)d_in[7];
    const float* W1 = (const float*)d_in[8];
    const float* b1 = (const float*)d_in[9];
    const float* W2 = (const float*)d_in[10];
    const float* b2 = (const float*)d_in[11];
    float* out = (float*)d_out;

    bf16 *xh,*xl,*qh,*ql,*kh,*kl,*vh,*vl,*oh,*ol,*h1h,*h1l;
    bf16 *wqh,*wql,*wkh,*wkl,*wvh,*wvl,*w1h,*w1l,*w2h,*w2l,*wh,*wl;
    float *sc, *of;
    cudaGetSymbolAddress((void**)&xh,  g_xh);  cudaGetSymbolAddress((void**)&xl,  g_xl);
    cudaGetSymbolAddress((void**)&qh,  g_qh);  cudaGetSymbolAddress((void**)&ql,  g_ql);
    cudaGetSymbolAddress((void**)&kh,  g_kh);  cudaGetSymbolAddress((void**)&kl,  g_kl);
    cudaGetSymbolAddress((void**)&vh,  g_vh);  cudaGetSymbolAddress((void**)&vl,  g_vl);
    cudaGetSymbolAddress((void**)&oh,  g_oh);  cudaGetSymbolAddress((void**)&ol,  g_ol);
    cudaGetSymbolAddress((void**)&h1h, g_h1h); cudaGetSymbolAddress((void**)&h1l, g_h1l);
    cudaGetSymbolAddress((void**)&wqh, g_wqh); cudaGetSymbolAddress((void**)&wql, g_wql);
    cudaGetSymbolAddress((void**)&wkh, g_wkh); cudaGetSymbolAddress((void**)&wkl, g_wkl);
    cudaGetSymbolAddress((void**)&wvh, g_wvh); cudaGetSymbolAddress((void**)&wvl, g_wvl);
    cudaGetSymbolAddress((void**)&w1h, g_w1h); cudaGetSymbolAddress((void**)&w1l, g_w1l);
    cudaGetSymbolAddress((void**)&w2h, g_w2h); cudaGetSymbolAddress((void**)&w2l, g_w2l);
    cudaGetSymbolAddress((void**)&wh,  g_wh);  cudaGetSymbolAddress((void**)&wl,  g_wl);
    cudaGetSymbolAddress((void**)&sc,  g_sc);
    cudaGetSymbolAddress((void**)&of,  g_of);

    cudaFuncSetAttribute(gemm_bf, cudaFuncAttributeMaxDynamicSharedMemorySize, SMEM_GEMM);

    /* pre-convert x and weights to bf16 hi/lo */
    cvt_kernel<<<(NXE/2 + 255)/256, 256>>>(x,  (uint32_t*)xh,  (uint32_t*)xl,  NXE/2);
    cvt_kernel<<<(NWE/2 + 255)/256, 256>>>(Wq, (uint32_t*)wqh, (uint32_t*)wql, NWE/2);
    cvt_kernel<<<(NWE/2 + 255)/256, 256>>>(Wk, (uint32_t*)wkh, (uint32_t*)wkl, NWE/2);
    cvt_kernel<<<(NWE/2 + 255)/256, 256>>>(Wv, (uint32_t*)wvh, (uint32_t*)wvl, NWE/2);
    cvt_kernel<<<(NWE/2 + 255)/256, 256>>>(W1, (uint32_t*)w1h, (uint32_t*)w1l, NWE/2);
    cvt_kernel<<<(NWE/2 + 255)/256, 256>>>(W2, (uint32_t*)w2h, (uint32_t*)w2l, NWE/2);

    dim3 blk(NTHREADS);
    const size_t sBH = (size_t)SEQ * HID, sBS = (size_t)SEQ * SEQ;
    dim3 gproj(HID / BN, (NB * SEQ) / BM, 1);
    dim3 gsc(SEQ / BN, SEQ / BM, NB);
    dim3 gpv(HID / BN, SEQ / BM, NB);

    /* q,k,v projections (NT vs weights) */
    gemm_bf<<<gproj, blk, SMEM_GEMM>>>(xh, xl, wqh, wql, HID, 0, 0, 0, 0, 0,
        nullptr, qh, ql, HID, bq, nullptr, nullptr, 1);
    gemm_bf<<<gproj, blk, SMEM_GEMM>>>(xh, xl, wkh, wkl, HID, 0, 0, 0, 0, 0,
        nullptr, kh, kl, HID, bk, nullptr, nullptr, 1);
    gemm_bf<<<gproj, blk, SMEM_GEMM>>>(xh, xl, wvh, wvl, HID, 0, 0, 0, 0, 0,
        nullptr, vh, vl, HID, bv, nullptr, nullptr, 0);

    /* scores = q k^T * scale - mask penalty (fp32 out) */
    gemm_bf<<<gsc, blk, SMEM_GEMM>>>(qh, ql, kh, kl, HID, 0, 0, sBH, sBH, sBS,
        sc, nullptr, nullptr, SEQ, nullptr, nullptr, mask, 0);

    softmax_kernel<<<dim3(SEQ, NB), 256>>>(sc, wh, wl, mask);

    /* O = W V  (NN: B = v[t][h]) */
    gemm_bf<<<gpv, blk, SMEM_GEMM>>>(wh, wl, vh, vl, SEQ, 1, HID, sBS, sBH, sBH,
        of, oh, ol, HID, nullptr, nullptr, nullptr, 0);

    /* FFN */
    gemm_bf<<<gproj, blk, SMEM_GEMM>>>(oh, ol, w1h, w1l, HID, 0, 0, 0, 0, 0,
        nullptr, h1h, h1l, HID, b1, nullptr, nullptr, 1);
    gemm_bf<<<gproj, blk, SMEM_GEMM>>>(h1h, h1l, w2h, w2l, HID, 0, 0, 0, 0, 0,
        out, nullptr, nullptr, HID, b2, of, nullptr, 0);
}

// round 5
// speedup vs baseline: 2.6163x; 1.1211x over previous
#include <cuda_runtime.h>
#include <cuda_bf16.h>
#include <cstdint>

#define NB   16
#define SEQ  1024
#define HID  768
#define SCALE_QK 0.03608439182435161f

#define BM 128
#define BN 128
#define BK 32
#define NTHREADS 256
#define STG 10240            /* bytes per hi or lo tile buffer */
#define STAGE_BYTES 40960    /* Ah,Al,Bh,Bl */
#define NSTAGES 2
#define SMEM_GEMM (NSTAGES*STAGE_BYTES)

typedef __nv_bfloat16 bf16;

/* ------------------ scratch (device globals) ------------------ */
#define NXE 12582912   /* 16*1024*768 */
#define NWE 589824     /* 768*768 */
#define NSE 16777216   /* 16*1024*1024 */
__device__ bf16 g_xh[NXE],  g_xl[NXE];
__device__ bf16 g_qh[NXE],  g_ql[NXE];
__device__ bf16 g_kh[NXE],  g_kl[NXE];
__device__ bf16 g_vh[NXE],  g_vl[NXE];
__device__ bf16 g_oh[NXE],  g_ol[NXE];
__device__ bf16 g_h1h[NXE], g_h1l[NXE];
__device__ bf16 g_wqh[NWE], g_wql[NWE], g_wkh[NWE], g_wkl[NWE], g_wvh[NWE], g_wvl[NWE];
__device__ bf16 g_w1h[NWE], g_w1l[NWE], g_w2h[NWE], g_w2l[NWE];
__device__ float g_sc[NSE];
__device__ bf16 g_wh[NSE],  g_wl[NSE];
__device__ float g_of[NXE];

/* ------------------ helpers ------------------ */
static __device__ __forceinline__ uint32_t smem_u32(const void* p) {
    uint32_t a;
    asm("{ .reg .u64 t; cvta.to.shared.u64 t, %1; cvt.u32.u64 %0, t; }" : "=r"(a) : "l"(p));
    return a;
}
static __device__ __forceinline__ uint32_t pack_bf2(float v0, float v1) {
    uint32_t d;  /* memory order v0,v1 */
    asm("cvt.rn.bf16x2.f32 %0, %1, %2;" : "=r"(d) : "f"(v1), "f"(v0));
    return d;
}
static __device__ __forceinline__ void split2(float v0, float v1, uint32_t& h, uint32_t& l) {
    h = pack_bf2(v0, v1);
    float h0 = __uint_as_float(h << 16);
    float h1 = __uint_as_float(h & 0xFFFF0000u);
    l = pack_bf2(v0 - h0, v1 - h1);
}

#define CP16(dst, src) \
    asm volatile("cp.async.cg.shared.global [%0], [%1], 16;" :: "r"(dst), "l"(src))
#define CPCOMMIT() asm volatile("cp.async.commit_group;" ::: "memory")
#define CPWAIT1()  asm volatile("cp.async.wait_group 1;" ::: "memory")

#define LDSM4(r, a) \
    asm volatile("ldmatrix.sync.aligned.m8n8.x4.shared.b16 {%0,%1,%2,%3}, [%4];" \
        : "=r"((r)[0]),"=r"((r)[1]),"=r"((r)[2]),"=r"((r)[3]) : "r"(a))
#define LDSM4T(r, a) \
    asm volatile("ldmatrix.sync.aligned.m8n8.x4.trans.shared.b16 {%0,%1,%2,%3}, [%4];" \
        : "=r"((r)[0]),"=r"((r)[1]),"=r"((r)[2]),"=r"((r)[3]) : "r"(a))
#define MMA(c, a, b0, b1) \
    asm volatile("mma.sync.aligned.m16n8k16.row.col.f32.bf16.bf16.f32 " \
        "{%0,%1,%2,%3}, {%4,%5,%6,%7}, {%8,%9}, {%0,%1,%2,%3};" \
        : "+f"((c)[0]), "+f"((c)[1]), "+f"((c)[2]), "+f"((c)[3]) \
        : "r"((a)[0]),"r"((a)[1]),"r"((a)[2]),"r"((a)[3]), "r"(b0), "r"(b1))

/* fp32 -> bf16 hi/lo conversion (pre-pass) */
__global__ __launch_bounds__(256) void cvt_kernel(
    const float* __restrict__ in, uint32_t* __restrict__ oh,
    uint32_t* __restrict__ ol, int n2)
{
    int i = blockIdx.x * 256 + threadIdx.x;
    if (i < n2) {
        float2 v = reinterpret_cast<const float2*>(in)[i];
        uint32_t h, l; split2(v.x, v.y, h, l);
        oh[i] = h; ol[i] = l;
    }
}

/* ---------------------------------------------------------------------------
 * bf16 split GEMM, mma.sync m16n8k16, 128x128x32 tiles, 2-stage cp.async,
 * 2 CTAs/SM for cross-CTA latency hiding.
 * nn=0: C = A[M,K] * B[N,K]^T ; nn=1: C = A[M,K] * B[K,N] (ldbn = row stride).
 * ------------------------------------------------------------------------ */
__global__ __launch_bounds__(NTHREADS, 2) void gemm_bf(
    const bf16* __restrict__ Ah, const bf16* __restrict__ Al,
    const bf16* __restrict__ Bh, const bf16* __restrict__ Bl,
    int K, int nn, int ldbn,
    size_t sA, size_t sB, size_t sC,
    float* __restrict__ Cf, bf16* __restrict__ Ch, bf16* __restrict__ Cl,
    int ldc, const float* __restrict__ bias, const float* __restrict__ res,
    const int* __restrict__ mask, int relu)
{
    extern __shared__ char smraw[];
    const uint32_t sb = smem_u32(smraw);
    const int tid = threadIdx.x, lane = tid & 31, wid = tid >> 5;
    const int wm = wid >> 1, wn = wid & 1;
    const int z = blockIdx.z, bm = blockIdx.y * BM, bn = blockIdx.x * BN;

    const bf16* Ahg = Ah + z * sA + (size_t)bm * K;
    const bf16* Alg = Al + z * sA + (size_t)bm * K;
    const bf16 *Bhg, *Blg;
    if (nn) { Bhg = Bh + z * sB + bn;              Blg = Bl + z * sB + bn; }
    else    { Bhg = Bh + z * sB + (size_t)bn * K;  Blg = Bl + z * sB + (size_t)bn * K; }

    float acc[2][8][4];
    #pragma unroll
    for (int i = 0; i < 2; i++)
        #pragma unroll
        for (int j = 0; j < 8; j++)
            #pragma unroll
            for (int t = 0; t < 4; t++) acc[i][j][t] = 0.f;

    auto issue = [&](int s) {
        const uint32_t stb = sb + (uint32_t)(s & 1) * STAGE_BYTES;
        const int k0 = s * BK;
        #pragma unroll
        for (int i = 0; i < 2; i++) {
            const int idx = tid + (i << 8);
            const int row = idx >> 2, c8 = (idx & 3) << 3;
            const uint32_t da = stb + row * 80 + (c8 << 1);
            CP16(da,       Ahg + (size_t)row * K + k0 + c8);
            CP16(da + STG, Alg + (size_t)row * K + k0 + c8);
        }
        if (!nn) {
            #pragma unroll
            for (int i = 0; i < 2; i++) {
                const int idx = tid + (i << 8);
                const int row = idx >> 2, c8 = (idx & 3) << 3;
                const uint32_t db = stb + 2 * STG + row * 80 + (c8 << 1);
                CP16(db,       Bhg + (size_t)row * K + k0 + c8);
                CP16(db + STG, Blg + (size_t)row * K + k0 + c8);
            }
        } else {
            #pragma unroll
            for (int i = 0; i < 2; i++) {
                const int idx = tid + (i << 8);
                const int row = idx >> 4, c8 = (idx & 15) << 3;
                const uint32_t db = stb + 2 * STG + row * 272 + (c8 << 1);
                CP16(db,       Bhg + (size_t)(k0 + row) * ldbn + c8);
                CP16(db + STG, Blg + (size_t)(k0 + row) * ldbn + c8);
            }
        }
    };

    auto compute = [&](int s) {
        const uint32_t stb = sb + (uint32_t)(s & 1) * STAGE_BYTES;
        #pragma unroll
        for (int ks = 0; ks < 2; ks++) {
            uint32_t ah[2][4], al[2][4];
            #pragma unroll
            for (int i = 0; i < 2; i++) {
                const int arow = wm * 32 + i * 16 + (lane & 15);
                const uint32_t ad = stb + arow * 80 + ((ks * 16 + ((lane >> 4) << 3)) << 1);
                LDSM4(ah[i], ad);
                LDSM4(al[i], ad + STG);
            }
            #pragma unroll
            for (int p = 0; p < 4; p++) {
                uint32_t bh[4], bl[4];
                if (!nn) {
                    const int brow = wn * 64 + p * 16 + (lane & 7) + ((lane >> 4) << 3);
                    const uint32_t bd = stb + 2 * STG + brow * 80 +
                                        ((ks * 16 + (((lane >> 3) & 1) << 3)) << 1);
                    LDSM4(bh, bd);
                    LDSM4(bl, bd + STG);
                } else {
                    const int krow = ks * 16 + (lane & 7) + (((lane >> 3) & 1) << 3);
                    const int ncol = wn * 64 + p * 16 + ((lane >> 4) << 3);
                    const uint32_t bd = stb + 2 * STG + krow * 272 + (ncol << 1);
                    LDSM4T(bh, bd);
                    LDSM4T(bl, bd + STG);
                }
                #pragma unroll
                for (int i = 0; i < 2; i++)
                    #pragma unroll
                    for (int jj = 0; jj < 2; jj++) {
                        const int j = p * 2 + jj;
                        MMA(acc[i][j], ah[i], bh[jj * 2], bh[jj * 2 + 1]);
                        MMA(acc[i][j], ah[i], bl[jj * 2], bl[jj * 2 + 1]);
                        MMA(acc[i][j], al[i], bh[jj * 2], bh[jj * 2 + 1]);
                    }
            }
        }
    };

    const int NSt = K / BK;
    issue(0); CPCOMMIT();
    for (int s = 0; s < NSt; s++) {
        if (s + 1 < NSt) issue(s + 1);
        CPCOMMIT();
        CPWAIT1();
        __syncthreads();
        compute(s);
        __syncthreads();
    }

    /* ---- epilogue ---- */
    const int* mk = mask ? (mask + (size_t)z * SEQ) : (const int*)0;
    float* Cfz = Cf ? (Cf + z * sC) : (float*)0;
    bf16*  Chz = Ch ? (Ch + z * sC) : (bf16*)0;
    bf16*  Clz = Cl ? (Cl + z * sC) : (bf16*)0;
    const float* rz = res ? (res + z * sC) : (const float*)0;

    #pragma unroll
    for (int i = 0; i < 2; i++) {
        const int r0 = bm + wm * 32 + i * 16 + (lane >> 2);
        #pragma unroll
        for (int j = 0; j < 8; j++) {
            const int c = bn + wn * 64 + j * 8 + ((lane & 3) << 1);
            float ax = acc[i][j][0], ay = acc[i][j][1];
            float az = acc[i][j][2], aw = acc[i][j][3];
            if (mk) {
                const float mc0 = (float)mk[c], mc1 = (float)mk[c + 1];
                const float m0 = (float)mk[r0], m1 = (float)mk[r0 + 8];
                ax = ax * SCALE_QK - (1.f - m0 * mc0) * 1e12f;
                ay = ay * SCALE_QK - (1.f - m0 * mc1) * 1e12f;
                az = az * SCALE_QK - (1.f - m1 * mc0) * 1e12f;
                aw = aw * SCALE_QK - (1.f - m1 * mc1) * 1e12f;
            } else {
                if (bias) {
                    const float b0 = bias[c], b1 = bias[c + 1];
                    ax += b0; ay += b1; az += b0; aw += b1;
                }
                if (relu) {
                    ax = fmaxf(ax, 0.f); ay = fmaxf(ay, 0.f);
                    az = fmaxf(az, 0.f); aw = fmaxf(aw, 0.f);
                }
                if (rz) {
                    const float2 q0 = *(const float2*)&rz[(size_t)r0 * ldc + c];
                    const float2 q1 = *(const float2*)&rz[(size_t)(r0 + 8) * ldc + c];
                    ax += q0.x; ay += q0.y; az += q1.x; aw += q1.y;
                }
            }
            const size_t o0 = (size_t)r0 * ldc + c, o1 = o0 + (size_t)8 * ldc;
            if (Cfz) {
                *(float2*)&Cfz[o0] = make_float2(ax, ay);
                *(float2*)&Cfz[o1] = make_float2(az, aw);
            }
            if (Chz) {
                uint32_t h, l;
                split2(ax, ay, h, l);
                *(uint32_t*)((char*)Chz + o0 * 2) = h;
                *(uint32_t*)((char*)Clz + o0 * 2) = l;
                split2(az, aw, h, l);
                *(uint32_t*)((char*)Chz + o1 * 2) = h;
                *(uint32_t*)((char*)Clz + o1 * 2) = l;
            }
        }
    }
}

/* ---- row softmax, fp32 in -> bf16 hi/lo out, fused mask ---- */
__global__ __launch_bounds__(256) void softmax_kernel(
    const float* __restrict__ Sc, bf16* __restrict__ Wh, bf16* __restrict__ Wl,
    const int* __restrict__ mask)
{
    const int b = blockIdx.y, row = blockIdx.x, tid = threadIdx.x;
    const float* srow = Sc + ((size_t)b * SEQ + row) * SEQ;
    const int* mrow = mask + (size_t)b * SEQ;
    float4 x = *(const float4*)(srow + tid * 4);

    float mx = fmaxf(fmaxf(x.x, x.y), fmaxf(x.z, x.w));
    #pragma unroll
    for (int o = 16; o > 0; o >>= 1) mx = fmaxf(mx, __shfl_xor_sync(~0u, mx, o));
    __shared__ float red[8];
    if ((tid & 31) == 0) red[tid >> 5] = mx;
    __syncthreads();
    float rmx = red[0];
    #pragma unroll
    for (int i = 1; i < 8; i++) rmx = fmaxf(rmx, red[i]);

    float e0 = expf(x.x - rmx), e1 = expf(x.y - rmx);
    float e2 = expf(x.z - rmx), e3 = expf(x.w - rmx);
    float s = e0 + e1 + e2 + e3;
    #pragma unroll
    for (int o = 16; o > 0; o >>= 1) s += __shfl_xor_sync(~0u, s, o);
    __syncthreads();
    if ((tid & 31) == 0) red[tid >> 5] = s;
    __syncthreads();
    float tot = red[0];
    #pragma unroll
    for (int i = 1; i < 8; i++) tot += red[i];

    const float cns = (1.0f / tot) * (float)mrow[row];
    const float o0 = e0 * cns * (float)mrow[tid * 4 + 0];
    const float o1 = e1 * cns * (float)mrow[tid * 4 + 1];
    const float o2 = e2 * cns * (float)mrow[tid * 4 + 2];
    const float o3 = e3 * cns * (float)mrow[tid * 4 + 3];

    uint32_t h0, l0, h1, l1;
    split2(o0, o1, h0, l0);
    split2(o2, o3, h1, l1);
    const size_t off = (((size_t)b * SEQ + row) * SEQ + tid * 4) * 2;
    *(uint2*)((char*)Wh + off) = make_uint2(h0, h1);
    *(uint2*)((char*)Wl + off) = make_uint2(l0, l1);
}

/* --------------------------------------------------------------------- */
extern "C" void kernel_launch(void* const* d_in, const int* in_sizes, int n_in,
                              void* d_out, int out_size)
{
    const float* x    = (const float*)d_in[0];
    const int*   mask = (const int*)  d_in[1];
    const float* Wq = (const float*)d_in[2];
    const float* bq = (const float*)d_in[3];
    const float* Wk = (const float*)d_in[4];
    const float* bk = (const float*)d_in[5];
    const float* Wv = (const float*)d_in[6];
    const float* bv = (const float*)d_in[7];
    const float* W1 = (const float*)d_in[8];
    const float* b1 = (const float*)d_in[9];
    const float* W2 = (const float*)d_in[10];
    const float* b2 = (const float*)d_in[11];
    float* out = (float*)d_out;

    bf16 *xh,*xl,*qh,*ql,*kh,*kl,*vh,*vl,*oh,*ol,*h1h,*h1l;
    bf16 *wqh,*wql,*wkh,*wkl,*wvh,*wvl,*w1h,*w1l,*w2h,*w2l,*wh,*wl;
    float *sc, *of;
    cudaGetSymbolAddress((void**)&xh,  g_xh);  cudaGetSymbolAddress((void**)&xl,  g_xl);
    cudaGetSymbolAddress((void**)&qh,  g_qh);  cudaGetSymbolAddress((void**)&ql,  g_ql);
    cudaGetSymbolAddress((void**)&kh,  g_kh);  cudaGetSymbolAddress((void**)&kl,  g_kl);
    cudaGetSymbolAddress((void**)&vh,  g_vh);  cudaGetSymbolAddress((void**)&vl,  g_vl);
    cudaGetSymbolAddress((void**)&oh,  g_oh);  cudaGetSymbolAddress((void**)&ol,  g_ol);
    cudaGetSymbolAddress((void**)&h1h, g_h1h); cudaGetSymbolAddress((void**)&h1l, g_h1l);
    cudaGetSymbolAddress((void**)&wqh, g_wqh); cudaGetSymbolAddress((void**)&wql, g_wql);
    cudaGetSymbolAddress((void**)&wkh, g_wkh); cudaGetSymbolAddress((void**)&wkl, g_wkl);
    cudaGetSymbolAddress((void**)&wvh, g_wvh); cudaGetSymbolAddress((void**)&wvl, g_wvl);
    cudaGetSymbolAddress((void**)&w1h, g_w1h); cudaGetSymbolAddress((void**)&w1l, g_w1l);
    cudaGetSymbolAddress((void**)&w2h, g_w2h); cudaGetSymbolAddress((void**)&w2l, g_w2l);
    cudaGetSymbolAddress((void**)&wh,  g_wh);  cudaGetSymbolAddress((void**)&wl,  g_wl);
    cudaGetSymbolAddress((void**)&sc,  g_sc);
    cudaGetSymbolAddress((void**)&of,  g_of);

    cudaFuncSetAttribute(gemm_bf, cudaFuncAttributeMaxDynamicSharedMemorySize, SMEM_GEMM);

    /* pre-convert x and weights to bf16 hi/lo */
    cvt_kernel<<<(NXE/2 + 255)/256, 256>>>(x,  (uint32_t*)xh,  (uint32_t*)xl,  NXE/2);
    cvt_kernel<<<(NWE/2 + 255)/256, 256>>>(Wq, (uint32_t*)wqh, (uint32_t*)wql, NWE/2);
    cvt_kernel<<<(NWE/2 + 255)/256, 256>>>(Wk, (uint32_t*)wkh, (uint32_t*)wkl, NWE/2);
    cvt_kernel<<<(NWE/2 + 255)/256, 256>>>(Wv, (uint32_t*)wvh, (uint32_t*)wvl, NWE/2);
    cvt_kernel<<<(NWE/2 + 255)/256, 256>>>(W1, (uint32_t*)w1h, (uint32_t*)w1l, NWE/2);
    cvt_kernel<<<(NWE/2 + 255)/256, 256>>>(W2, (uint32_t*)w2h, (uint32_t*)w2l, NWE/2);

    dim3 blk(NTHREADS);
    const size_t sBH = (size_t)SEQ * HID, sBS = (size_t)SEQ * SEQ;
    dim3 gproj(HID / BN, (NB * SEQ) / BM, 1);
    dim3 gsc(SEQ / BN, SEQ / BM, NB);
    dim3 gpv(HID / BN, SEQ / BM, NB);

    /* q,k,v projections (NT vs weights) */
    gemm_bf<<<gproj, blk, SMEM_GEMM>>>(xh, xl, wqh, wql, HID, 0, 0, 0, 0, 0,
        nullptr, qh, ql, HID, bq, nullptr, nullptr, 1);
    gemm_bf<<<gproj, blk, SMEM_GEMM>>>(xh, xl, wkh, wkl, HID, 0, 0, 0, 0, 0,
        nullptr, kh, kl, HID, bk, nullptr, nullptr, 1);
    gemm_bf<<<gproj, blk, SMEM_GEMM>>>(xh, xl, wvh, wvl, HID, 0, 0, 0, 0, 0,
        nullptr, vh, vl, HID, bv, nullptr, nullptr, 0);

    /* scores = q k^T * scale - mask penalty (fp32 out) */
    gemm_bf<<<gsc, blk, SMEM_GEMM>>>(qh, ql, kh, kl, HID, 0, 0, sBH, sBH, sBS,
        sc, nullptr, nullptr, SEQ, nullptr, nullptr, mask, 0);

    softmax_kernel<<<dim3(SEQ, NB), 256>>>(sc, wh, wl, mask);

    /* O = W V  (NN: B = v[t][h]) */
    gemm_bf<<<gpv, blk, SMEM_GEMM>>>(wh, wl, vh, vl, SEQ, 1, HID, sBS, sBH, sBH,
        of, oh, ol, HID, nullptr, nullptr, nullptr, 0);

    /* FFN */
    gemm_bf<<<gproj, blk, SMEM_GEMM>>>(oh, ol, w1h, w1l, HID, 0, 0, 0, 0, 0,
        nullptr, h1h, h1l, HID, b1, nullptr, nullptr, 1);
    gemm_bf<<<gproj, blk, SMEM_GEMM>>>(h1h, h1l, w2h, w2l, HID, 0, 0, 0, 0, 0,
        out, nullptr, nullptr, HID, b2, of, nullptr, 0);
}